// round 9
// baseline (speedup 1.0000x reference)
#include <cuda_runtime.h>

// IF neuron: x [T=4, B=32, H=512, W=1024] fp32.
// v=0; for t: v += x[t][i]; s=(v>=1)?1:0; out[t][i]=s; v-=s;
// Pure HBM stream: 256 MB read + 256 MB write (mandatory).
// R9: same theory as R7 (256-bit accesses x 2 float8/plane/thread, grid 4096)
// but flattened into named registers — structurally closer to the known-good
// R6 source after two infra failures on the array-based variant.

#define T_STEPS 4
#define SPATIAL (32 * 512 * 1024)          // 16,777,216 floats per plane
#define PLANE8  (SPATIAL / 8)              // 2,097,152 float8 per plane
#define THREADS 256
#define ITEMS   2
#define BLOCKS  (PLANE8 / (THREADS * ITEMS))   // 4096, exact

struct __align__(32) f8 { float v[8]; };

__device__ __forceinline__ f8 ldg256(const float* p) {
    f8 r;
    asm volatile(
        "ld.global.nc.v8.f32 {%0,%1,%2,%3,%4,%5,%6,%7}, [%8];"
        : "=f"(r.v[0]), "=f"(r.v[1]), "=f"(r.v[2]), "=f"(r.v[3]),
          "=f"(r.v[4]), "=f"(r.v[5]), "=f"(r.v[6]), "=f"(r.v[7])
        : "l"(p));
    return r;
}

__device__ __forceinline__ void stg256(float* p, const f8& r) {
    asm volatile(
        "st.global.v8.f32 [%0], {%1,%2,%3,%4,%5,%6,%7,%8};"
        :: "l"(p),
           "f"(r.v[0]), "f"(r.v[1]), "f"(r.v[2]), "f"(r.v[3]),
           "f"(r.v[4]), "f"(r.v[5]), "f"(r.v[6]), "f"(r.v[7])
        : "memory");
}

// IF scan across 4 timesteps for one lane k of the f8 payload.
__device__ __forceinline__ void if_scan(
    const f8& a0, const f8& a1, const f8& a2, const f8& a3,
    f8& o0, f8& o1, f8& o2, f8& o3)
{
#pragma unroll
    for (int k = 0; k < 8; ++k) {
        float v = 0.f, s;
        v += a0.v[k]; s = (v >= 1.0f) ? 1.0f : 0.0f; o0.v[k] = s; v -= s;
        v += a1.v[k]; s = (v >= 1.0f) ? 1.0f : 0.0f; o1.v[k] = s; v -= s;
        v += a2.v[k]; s = (v >= 1.0f) ? 1.0f : 0.0f; o2.v[k] = s; v -= s;
        v += a3.v[k]; s = (v >= 1.0f) ? 1.0f : 0.0f; o3.v[k] = s;
    }
}

__global__ __launch_bounds__(THREADS) void if_neuron_kernel(
    const float* __restrict__ x, float* __restrict__ out)
{
    const size_t base8 = (size_t)blockIdx.x * (THREADS * ITEMS) + threadIdx.x;
    const size_t offA = base8 * 8;                      // chunk 0
    const size_t offB = (base8 + THREADS) * 8;          // chunk 1

    // Front-batched loads: 8 independent 256-bit loads.
    f8 xa0 = ldg256(x + 0 * (size_t)SPATIAL + offA);
    f8 xa1 = ldg256(x + 1 * (size_t)SPATIAL + offA);
    f8 xa2 = ldg256(x + 2 * (size_t)SPATIAL + offA);
    f8 xa3 = ldg256(x + 3 * (size_t)SPATIAL + offA);
    f8 xb0 = ldg256(x + 0 * (size_t)SPATIAL + offB);
    f8 xb1 = ldg256(x + 1 * (size_t)SPATIAL + offB);
    f8 xb2 = ldg256(x + 2 * (size_t)SPATIAL + offB);
    f8 xb3 = ldg256(x + 3 * (size_t)SPATIAL + offB);

    f8 sa0, sa1, sa2, sa3, sb0, sb1, sb2, sb3;
    if_scan(xa0, xa1, xa2, xa3, sa0, sa1, sa2, sa3);
    if_scan(xb0, xb1, xb2, xb3, sb0, sb1, sb2, sb3);

    // Back-batched stores: 8 independent 256-bit stores.
    stg256(out + 0 * (size_t)SPATIAL + offA, sa0);
    stg256(out + 0 * (size_t)SPATIAL + offB, sb0);
    stg256(out + 1 * (size_t)SPATIAL + offA, sa1);
    stg256(out + 1 * (size_t)SPATIAL + offB, sb1);
    stg256(out + 2 * (size_t)SPATIAL + offA, sa2);
    stg256(out + 2 * (size_t)SPATIAL + offB, sb2);
    stg256(out + 3 * (size_t)SPATIAL + offA, sa3);
    stg256(out + 3 * (size_t)SPATIAL + offB, sb3);
}

extern "C" void kernel_launch(void* const* d_in, const int* in_sizes, int n_in,
                              void* d_out, int out_size)
{
    const float* x = (const float*)d_in[0];
    float* out = (float*)d_out;
    if_neuron_kernel<<<BLOCKS, THREADS>>>(x, out);
}

// round 11
// speedup vs baseline: 1.0011x; 1.0011x over previous
#include <cuda_runtime.h>

// IF neuron: x [T=4, B=32, H=512, W=1024] fp32.
// v=0; for t: v += x[t][i]; s=(v>=1)?1:0; out[t][i]=s; v-=s;
// Pure HBM stream: 256 MB read + 256 MB write (mandatory traffic).
// R11: resubmit of R10 (infra flake, no signal). R6 structure (1 float8 per
// plane per thread, 256-bit ld/st — best measured form) with 512-thread
// blocks. Final launch-shape sweep cell; all other levers measured neutral.
// ~6.4 TB/s = chip LTS cap for this 1:1 R/W pattern.

#define T_STEPS 4
#define SPATIAL (32 * 512 * 1024)          // 16,777,216 floats per plane
#define PLANE8  (SPATIAL / 8)              // 2,097,152 float8 per plane
#define THREADS 512
#define BLOCKS  (PLANE8 / THREADS)         // 4096, exact

struct __align__(32) f8 { float v[8]; };

__device__ __forceinline__ f8 ldg256(const float* p) {
    f8 r;
    asm volatile(
        "ld.global.nc.v8.f32 {%0,%1,%2,%3,%4,%5,%6,%7}, [%8];"
        : "=f"(r.v[0]), "=f"(r.v[1]), "=f"(r.v[2]), "=f"(r.v[3]),
          "=f"(r.v[4]), "=f"(r.v[5]), "=f"(r.v[6]), "=f"(r.v[7])
        : "l"(p));
    return r;
}

__device__ __forceinline__ void stg256(float* p, const f8& r) {
    asm volatile(
        "st.global.v8.f32 [%0], {%1,%2,%3,%4,%5,%6,%7,%8};"
        :: "l"(p),
           "f"(r.v[0]), "f"(r.v[1]), "f"(r.v[2]), "f"(r.v[3]),
           "f"(r.v[4]), "f"(r.v[5]), "f"(r.v[6]), "f"(r.v[7])
        : "memory");
}

__global__ __launch_bounds__(THREADS) void if_neuron_kernel(
    const float* __restrict__ x, float* __restrict__ out)
{
    const size_t i8 = blockIdx.x * (size_t)THREADS + threadIdx.x;
    const size_t off = i8 * 8;

    // Front-batched 256-bit loads, one per timestep plane.
    f8 x0 = ldg256(x + 0 * (size_t)SPATIAL + off);
    f8 x1 = ldg256(x + 1 * (size_t)SPATIAL + off);
    f8 x2 = ldg256(x + 2 * (size_t)SPATIAL + off);
    f8 x3 = ldg256(x + 3 * (size_t)SPATIAL + off);

    f8 s0, s1, s2, s3;
#pragma unroll
    for (int k = 0; k < 8; ++k) {
        float v = 0.f, s;
        v += x0.v[k]; s = (v >= 1.0f) ? 1.0f : 0.0f; s0.v[k] = s; v -= s;
        v += x1.v[k]; s = (v >= 1.0f) ? 1.0f : 0.0f; s1.v[k] = s; v -= s;
        v += x2.v[k]; s = (v >= 1.0f) ? 1.0f : 0.0f; s2.v[k] = s; v -= s;
        v += x3.v[k]; s = (v >= 1.0f) ? 1.0f : 0.0f; s3.v[k] = s;
    }

    // Back-batched 256-bit stores.
    stg256(out + 0 * (size_t)SPATIAL + off, s0);
    stg256(out + 1 * (size_t)SPATIAL + off, s1);
    stg256(out + 2 * (size_t)SPATIAL + off, s2);
    stg256(out + 3 * (size_t)SPATIAL + off, s3);
}

extern "C" void kernel_launch(void* const* d_in, const int* in_sizes, int n_in,
                              void* d_out, int out_size)
{
    const float* x = (const float*)d_in[0];
    float* out = (float*)d_out;
    if_neuron_kernel<<<BLOCKS, THREADS>>>(x, out);
}